// round 10
// baseline (speedup 1.0000x reference)
#include <cuda_runtime.h>
#include <cstdint>

// Problem dims
#define Bv 64
#define Lv 512
#define Iv 256
#define Hv 512

// Partition: CG column groups x RG batch groups, persistent blocks
#define CG 32
#define RG 4
#define NBLK (CG*RG)
#define CPB 16     // cols per block  (Hv/CG)
#define BPB 16     // batches per block (Bv/RG)
#define NT 256     // threads per block
#define KCH 256    // k-chunk staged in smem

// Global state buffers, layout [k][batch] (batch fastest) for coalescing
__device__ float g_h [Hv*Bv];
__device__ float g_m [Hv*Bv];
__device__ float g_k1[Hv*Bv];
__device__ float g_k2[Hv*Bv];
__device__ float g_k3[Hv*Bv];
__device__ float g_ho[Hv*Bv];
__device__ unsigned g_bar[RG*32];   // one counter per batch group, 128B apart

// ---- group barrier: 32 blocks of one batch group ------------------------
__device__ __forceinline__ void gbar(unsigned* ctr, unsigned target) {
    __syncthreads();
    if (threadIdx.x == 0) {
        __threadfence();
        atomicAdd(ctr, 1u);
        while (*(volatile unsigned*)ctr < target) { }
        __threadfence();
    }
    __syncthreads();
}

__device__ __forceinline__ float sigm(float v) { return 1.0f / (1.0f + expf(-v)); }

// ---- single-accumulator GEMV over k=Hv, input staged via loader ---------
template <typename F>
__device__ __forceinline__ float gemv_h(const float* __restrict__ wrow,
                                        float* __restrict__ s_in,
                                        int tx, int tid, F ldr) {
    float acc = 0.0f;
    #pragma unroll
    for (int k0 = 0; k0 < Hv; k0 += KCH) {
        __syncthreads();
        #pragma unroll
        for (int ii = 0; ii < (KCH*BPB)/NT; ii++) {
            int idx = tid + ii*NT;
            s_in[idx] = ldr(k0 + (idx >> 4), idx & 15);
        }
        __syncthreads();
        const float* wr = wrow + k0;
        #pragma unroll 8
        for (int j = 0; j < KCH; j++)
            acc = fmaf(wr[j], s_in[j*BPB + tx], acc);
    }
    return acc;
}

// ---- 3-accumulator GEMV (gates r,z,n share the staged input) ------------
template <int KD, bool KFAST, typename F>
__device__ __forceinline__ void gemv3(const float* __restrict__ w0,
                                      const float* __restrict__ w1,
                                      const float* __restrict__ w2,
                                      float* __restrict__ s_in,
                                      int tx, int tid, F ldr,
                                      float& a0, float& a1, float& a2) {
    #pragma unroll
    for (int k0 = 0; k0 < KD; k0 += KCH) {
        __syncthreads();
        #pragma unroll
        for (int ii = 0; ii < (KCH*BPB)/NT; ii++) {
            int idx = tid + ii*NT;
            int kk, bl;
            if (KFAST) { kk = idx % KCH; bl = idx / KCH; }   // k fast (coalesced x reads)
            else       { kk = idx >> 4;  bl = idx & 15;  }   // batch fast
            s_in[kk*BPB + bl] = ldr(k0 + kk, bl);
        }
        __syncthreads();
        #pragma unroll 4
        for (int j = 0; j < KCH; j++) {
            float v = s_in[j*BPB + tx];
            a0 = fmaf(w0[k0+j], v, a0);
            a1 = fmaf(w1[k0+j], v, a1);
            a2 = fmaf(w2[k0+j], v, a2);
        }
    }
}

__global__ void init_bar_kernel() {
    if (threadIdx.x < RG*32) g_bar[threadIdx.x] = 0;
}

__global__ void __launch_bounds__(NT, 1)
odegru_main(const float* __restrict__ x,     const float* __restrict__ tdel,
            const float* __restrict__ w_ih,  const float* __restrict__ w_hh,
            const float* __restrict__ b_ih,  const float* __restrict__ b_hh,
            const float* __restrict__ dw0,   const float* __restrict__ db0,
            const float* __restrict__ dw1,   const float* __restrict__ db1,
            const float* __restrict__ h0,    const int*   __restrict__ seq_lens,
            float* __restrict__ out) {
    extern __shared__ float smem[];
    float* s_dw0 = smem;                      // CPB*Hv
    float* s_dw1 = s_dw0 + CPB*Hv;            // CPB*Hv
    float* s_whh = s_dw1 + CPB*Hv;            // 3*CPB*Hv
    float* s_wih = s_whh + 3*CPB*Hv;          // 3*CPB*Iv
    float* s_in  = s_wih + 3*CPB*Iv;          // KCH*BPB
    float* s_td  = s_in + KCH*BPB;            // BPB
    float* s_act = s_td + BPB;                // BPB

    const int blk = blockIdx.x;
    const int cg  = blk & (CG-1);
    const int rg  = blk >> 5;                 // CG==32
    const int c0  = cg*CPB, b0 = rg*BPB;
    const int tid = threadIdx.x;
    const int tx  = tid & 15;                 // local batch
    const int ty  = tid >> 4;                 // local col
    const int c   = c0 + ty;
    const int b   = b0 + tx;

    // Persistent weight slices (rows contiguous in the source matrices)
    for (int i = tid; i < CPB*Hv; i += NT) {
        s_dw0[i] = dw0[c0*Hv + i];
        s_dw1[i] = dw1[c0*Hv + i];
    }
    #pragma unroll
    for (int g = 0; g < 3; g++) {
        for (int i = tid; i < CPB*Hv; i += NT)
            s_whh[g*CPB*Hv + i] = w_hh[(g*Hv + c0)*Hv + i];
        for (int i = tid; i < CPB*Iv; i += NT)
            s_wih[g*CPB*Iv + i] = w_ih[(g*Hv + c0)*Iv + i];
    }

    const float db0c = db0[c], db1c = db1[c];
    const float bhr = b_hh[c], bhz = b_hh[Hv+c], bhn = b_hh[2*Hv+c];
    const float bir = b_ih[c], biz = b_ih[Hv+c], bin_ = b_ih[2*Hv+c];
    const int   slen = seq_lens[b];

    // init hidden state
    g_h[c*Bv + b] = h0[c];

    unsigned* ctr = &g_bar[rg*32];
    unsigned nbar = 0;

    const float* wdw0 = s_dw0 + ty*Hv;
    const float* wdw1 = s_dw1 + ty*Hv;
    const float* whr  = s_whh + ty*Hv;
    const float* whz  = s_whh + (CPB  + ty)*Hv;
    const float* whn  = s_whh + (2*CPB+ ty)*Hv;
    const float* wir  = s_wih + ty*Iv;
    const float* wiz  = s_wih + (CPB  + ty)*Iv;
    const float* win  = s_wih + (2*CPB+ ty)*Iv;

    for (int t = 0; t < Lv; t++) {
        // publish previous h / init (group barrier), then set per-step td & mask
        gbar(ctr, (++nbar)*32);
        if (tid < BPB) {
            int bb = b0 + tid;
            float a = (t < seq_lens[bb]) ? 1.0f : 0.0f;
            s_act[tid] = a;
            s_td[tid]  = a * tdel[bb*Lv + t];
        }
        __syncthreads();
        const float tdv = s_td[tx];

        // ---- RK4 (3/8 rule), dt = 1 ----
        // S1: m = tanh(h @ dw0^T + db0)
        {
            float acc = gemv_h(wdw0, s_in, tx, tid,
                [&](int k, int bl){ return g_h[k*Bv + b0 + bl]; });
            g_m[c*Bv + b] = tanhf(acc + db0c);
        }
        gbar(ctr, (++nbar)*32);
        // S2: k1 = tanh(m @ dw1^T + db1) * td
        float k1v;
        {
            float acc = gemv_h(wdw1, s_in, tx, tid,
                [&](int k, int bl){ return g_m[k*Bv + b0 + bl]; });
            k1v = tanhf(acc + db1c) * tdv;
            g_k1[c*Bv + b] = k1v;
        }
        gbar(ctr, (++nbar)*32);
        // S3: m = tanh((h + k1/3) @ dw0^T + db0)
        {
            float acc = gemv_h(wdw0, s_in, tx, tid,
                [&](int k, int bl){ int i = k*Bv + b0 + bl;
                    return g_h[i] + (1.0f/3.0f)*g_k1[i]; });
            g_m[c*Bv + b] = tanhf(acc + db0c);
        }
        gbar(ctr, (++nbar)*32);
        // S4: k2
        float k2v;
        {
            float acc = gemv_h(wdw1, s_in, tx, tid,
                [&](int k, int bl){ return g_m[k*Bv + b0 + bl]; });
            k2v = tanhf(acc + db1c) * tdv;
            g_k2[c*Bv + b] = k2v;
        }
        gbar(ctr, (++nbar)*32);
        // S5: m = tanh((h + k2 - k1/3) @ dw0^T + db0)
        {
            float acc = gemv_h(wdw0, s_in, tx, tid,
                [&](int k, int bl){ int i = k*Bv + b0 + bl;
                    return g_h[i] + g_k2[i] - (1.0f/3.0f)*g_k1[i]; });
            g_m[c*Bv + b] = tanhf(acc + db0c);
        }
        gbar(ctr, (++nbar)*32);
        // S6: k3
        float k3v;
        {
            float acc = gemv_h(wdw1, s_in, tx, tid,
                [&](int k, int bl){ return g_m[k*Bv + b0 + bl]; });
            k3v = tanhf(acc + db1c) * tdv;
            g_k3[c*Bv + b] = k3v;
        }
        gbar(ctr, (++nbar)*32);
        // S7: m = tanh((h + k1 - k2 + k3) @ dw0^T + db0)
        {
            float acc = gemv_h(wdw0, s_in, tx, tid,
                [&](int k, int bl){ int i = k*Bv + b0 + bl;
                    return g_h[i] + g_k1[i] - g_k2[i] + g_k3[i]; });
            g_m[c*Bv + b] = tanhf(acc + db0c);
        }
        gbar(ctr, (++nbar)*32);
        // S8: k4 ; h_ode = h + (k1 + 3(k2+k3) + k4)/8
        float hov;
        {
            float acc = gemv_h(wdw1, s_in, tx, tid,
                [&](int k, int bl){ return g_m[k*Bv + b0 + bl]; });
            float k4v = tanhf(acc + db1c) * tdv;
            float hv  = g_h[c*Bv + b];
            hov = hv + (k1v + 3.0f*(k2v + k3v) + k4v) * 0.125f;
            g_ho[c*Bv + b] = hov;
        }
        gbar(ctr, (++nbar)*32);
        // S9: GRU cell — gh = h_ode @ w_hh^T, gi = x_t @ w_ih^T, gates, h_new
        {
            float ar = 0.f, az = 0.f, an = 0.f;
            gemv3<Hv, false>(whr, whz, whn, s_in, tx, tid,
                [&](int k, int bl){ return g_ho[k*Bv + b0 + bl]; },
                ar, az, an);
            float xr = 0.f, xz = 0.f, xn = 0.f;
            gemv3<Iv, true>(wir, wiz, win, s_in, tx, tid,
                [&](int k, int bl){
                    return s_act[bl] * x[(b0 + bl)*(Lv*Iv) + t*Iv + k]; },
                xr, xz, xn);
            float r = sigm((xr + bir) + (ar + bhr));
            float z = sigm((xz + biz) + (az + bhz));
            float n = tanhf((xn + bin_) + r * (an + bhn));
            float hn = (1.0f - z) * n + z * hov;
            g_h[c*Bv + b] = hn;
            out[b*(Lv*Hv) + t*Hv + c] = hn;
            if (t == slen - 1)
                out[Bv*Lv*Hv + b*Hv + c] = hn;
        }
        // next loop-top gbar publishes g_h for the following step
    }
}

extern "C" void kernel_launch(void* const* d_in, const int* in_sizes, int n_in,
                              void* d_out, int out_size) {
    const float* x     = (const float*)d_in[0];
    const float* tdel  = (const float*)d_in[1];
    const float* w_ih  = (const float*)d_in[2];
    const float* w_hh  = (const float*)d_in[3];
    const float* b_ih  = (const float*)d_in[4];
    const float* b_hh  = (const float*)d_in[5];
    const float* dw0   = (const float*)d_in[6];
    const float* db0   = (const float*)d_in[7];
    const float* dw1   = (const float*)d_in[8];
    const float* db1   = (const float*)d_in[9];
    const float* h0    = (const float*)d_in[10];
    const int*   seq   = (const int*)d_in[11];
    float* out = (float*)d_out;

    // smem: weights (53248 f) + s_in (KCH*BPB) + td/act (32 f)
    size_t smem_bytes = (size_t)(CPB*Hv*2 + 3*CPB*Hv + 3*CPB*Iv + KCH*BPB + 2*BPB) * sizeof(float);
    cudaFuncSetAttribute(odegru_main, cudaFuncAttributeMaxDynamicSharedMemorySize,
                         (int)smem_bytes);

    init_bar_kernel<<<1, 128>>>();
    odegru_main<<<NBLK, NT, smem_bytes>>>(x, tdel, w_ih, w_hh, b_ih, b_hh,
                                          dw0, db0, dw1, db1, h0, seq, out);
}

// round 11
// speedup vs baseline: 1.5708x; 1.5708x over previous
#include <cuda_runtime.h>
#include <cstdint>

#define Bv 64
#define Lv 512
#define Iv 256
#define Hv 512

#define CG 32
#define RG 4
#define NBLK (CG*RG)
#define CPB 16
#define BPB 16
#define NT 256

#define PH 516     // pitch for K=512 rows: 516 mod 32 == 4 -> conflict-free LDS.128
#define PI 260     // pitch for K=256 rows

typedef unsigned long long ull;

// Global state, layout [b][k] (k contiguous)
__device__ float g_h [Bv*Hv];
__device__ float g_m [Bv*Hv];
__device__ float g_k1[Bv*Hv];
__device__ float g_k2[Bv*Hv];
__device__ float g_k3[Bv*Hv];
__device__ float g_ho[Bv*Hv];
__device__ unsigned g_bar[RG*32];

__device__ __forceinline__ void ffma2(ull& acc, ull a, ull b) {
    asm("fma.rn.f32x2 %0, %1, %2, %0;" : "+l"(acc) : "l"(a), "l"(b));
}
__device__ __forceinline__ float lo32(ull v){ return __int_as_float((int)(unsigned)v); }
__device__ __forceinline__ float hi32(ull v){ return __int_as_float((int)(unsigned)(v>>32)); }
__device__ __forceinline__ float hsum1(ull a){ return lo32(a)+hi32(a); }
__device__ __forceinline__ float sigm(float v){ return 1.0f/(1.0f+expf(-v)); }

__device__ __forceinline__ void gbar(unsigned* ctr, unsigned target) {
    __syncthreads();
    if (threadIdx.x == 0) {
        __threadfence();
        atomicAdd(ctr, 1u);
        while (*(volatile unsigned*)ctr < target) { }
        __threadfence();
    }
    __syncthreads();
}

// stage 16 rows x 512 k into even/odd-batch smem (pitch PH), float4 everywhere
template <typename F>
__device__ __forceinline__ void stage512(float* __restrict__ sE, float* __restrict__ sO,
                                         int tid, F ld) {
    #pragma unroll
    for (int ii = 0; ii < 8; ii++) {
        int item = tid + ii*NT;          // 2048 float4 items
        int bb = item >> 7;              // 0..15
        int k4 = (item & 127) << 2;      // 0..508
        float4 v = ld(bb, k4);
        float* dst = ((bb & 1) ? sO : sE) + (bb >> 1)*PH + k4;
        *(float4*)dst = v;
    }
}

// K=256 slice GEMV: packed f32x2, 2 batches, 2 chains each
__device__ __forceinline__ void gemv256(const float* __restrict__ wrow,
                                        const float* __restrict__ rE,
                                        const float* __restrict__ rO,
                                        float& sE, float& sO) {
    const ulonglong2* __restrict__ w2 = (const ulonglong2*)wrow;
    const ulonglong2* __restrict__ e2 = (const ulonglong2*)rE;
    const ulonglong2* __restrict__ o2 = (const ulonglong2*)rO;
    ull aE0=0, aE1=0, aO0=0, aO1=0;
    #pragma unroll 16
    for (int j = 0; j < 64; j++) {
        ulonglong2 w = w2[j];
        ulonglong2 e = e2[j];
        ulonglong2 o = o2[j];
        ffma2(aE0, w.x, e.x); ffma2(aE1, w.y, e.y);
        ffma2(aO0, w.x, o.x); ffma2(aO1, w.y, o.y);
    }
    sE = hsum1(aE0) + hsum1(aE1);
    sO = hsum1(aO0) + hsum1(aO1);
}

// stage + gemv + K-split reduce + epilogue (epi runs on tid<128 with full sums)
template <typename FL, typename FE>
__device__ __forceinline__ void do_stage(const float* __restrict__ w,
                                         float* sE, float* sO,
                                         const float* inE, const float* inO,
                                         float* s_red, int tid, FL ld, FE epi) {
    stage512(sE, sO, tid, ld);
    __syncthreads();
    float vE, vO;
    gemv256(w, inE, inO, vE, vO);
    if (tid >= 128) ((float2*)s_red)[tid-128] = make_float2(vE, vO);
    __syncthreads();
    if (tid < 128) {
        float2 o = ((float2*)s_red)[tid];
        epi(vE + o.x, vO + o.y);
    }
}

__global__ void init_bar_kernel() {
    if (threadIdx.x < RG*32) g_bar[threadIdx.x] = 0;
}

__global__ void __launch_bounds__(NT, 1)
odegru_main(const float* __restrict__ x,     const float* __restrict__ tdel,
            const float* __restrict__ w_ih,  const float* __restrict__ w_hh,
            const float* __restrict__ b_ih,  const float* __restrict__ b_hh,
            const float* __restrict__ dw0,   const float* __restrict__ db0,
            const float* __restrict__ dw1,   const float* __restrict__ db1,
            const float* __restrict__ h0,    const int*   __restrict__ seq_lens,
            float* __restrict__ out) {
    extern __shared__ float smem[];
    float* s_dw0 = smem;                    // 16*PH
    float* s_dw1 = s_dw0 + CPB*PH;
    float* s_whh = s_dw1 + CPB*PH;          // 3*16*PH
    float* s_inE = s_whh + 3*CPB*PH;        // 8*PH
    float* s_inO = s_inE + 8*PH;
    float* s_xE  = s_inO + 8*PH;            // 8*PI
    float* s_xO  = s_xE + 8*PI;
    float* s_red = s_xO + 8*PI;             // 1024 floats (4 x 128 float2)
    float* s_td  = s_red + 1024;            // 16
    float* s_act = s_td + 16;               // 16

    const int blk = blockIdx.x;
    const int cg  = blk & (CG-1);
    const int rg  = blk >> 5;
    const int c0  = cg*CPB, b0 = rg*BPB;
    const int tid = threadIdx.x;

    const int wid    = tid >> 5;
    const int lane   = tid & 31;
    const int q      = wid & 3;
    const int kh     = wid >> 2;         // K half
    const int colIdx = lane & 3;
    const int p      = lane >> 2;        // batch pair
    const int c_loc  = (q<<2) + colIdx;
    const int c      = c0 + c_loc;
    const int bE     = p<<1, bO = bE+1;
    const int kbase  = kh << 8;

    // persistent weight slices (float4, pitch PH)
    #pragma unroll
    for (int ii = 0; ii < 8; ii++) {
        int item = tid + ii*NT;
        int r = item >> 7, k4 = (item & 127) << 2;
        *(float4*)&s_dw0[r*PH + k4] = *(const float4*)&dw0[(c0+r)*Hv + k4];
        *(float4*)&s_dw1[r*PH + k4] = *(const float4*)&dw1[(c0+r)*Hv + k4];
    }
    #pragma unroll
    for (int g = 0; g < 3; g++) {
        #pragma unroll
        for (int ii = 0; ii < 8; ii++) {
            int item = tid + ii*NT;
            int r = item >> 7, k4 = (item & 127) << 2;
            *(float4*)&s_whh[(g*CPB + r)*PH + k4] =
                *(const float4*)&w_hh[(g*Hv + c0 + r)*Hv + k4];
        }
    }

    const float db0c = db0[c], db1c = db1[c];
    const float bhr = b_hh[c], bhz = b_hh[Hv+c], bhn = b_hh[2*Hv+c];
    const float bir = b_ih[c], biz = b_ih[Hv+c], bin_ = b_ih[2*Hv+c];
    const int slenE = seq_lens[b0+bE], slenO = seq_lens[b0+bO];

    {   // init hidden state (block owns its 16x16 tile)
        int ty_i = tid >> 4, tx_i = tid & 15;
        g_h[(b0+tx_i)*Hv + (c0+ty_i)] = h0[c0+ty_i];
    }

    unsigned* ctr = &g_bar[rg*32];
    unsigned nbar = 0;

    const float* wD0 = s_dw0 + c_loc*PH + kbase;
    const float* wD1 = s_dw1 + c_loc*PH + kbase;
    const float* inE = s_inE + p*PH + kbase;
    const float* inO = s_inO + p*PH + kbase;

    float k1E=0.f,k1O=0.f,k2E=0.f,k2O=0.f,k3E=0.f,k3O=0.f,hoE=0.f,hoO=0.f;

    for (int t = 0; t < Lv; t++) {
        gbar(ctr, (++nbar)*32);              // publishes previous h
        if (tid < BPB) {
            int bb = b0 + tid;
            float a = (t < seq_lens[bb]) ? 1.0f : 0.0f;
            s_act[tid] = a;
            s_td[tid]  = a * tdel[bb*Lv + t];
        }
        __syncthreads();
        const float tdE = s_td[bE], tdO = s_td[bO];

        // stage masked x_t (16 x 256), E/O split, pitch PI
        #pragma unroll
        for (int ii = 0; ii < 4; ii++) {
            int item = tid + ii*NT;
            int bb = item >> 6;
            int k4 = (item & 63) << 2;
            float a = s_act[bb];
            float4 v = *(const float4*)&x[(b0+bb)*(Lv*Iv) + t*Iv + k4];
            v.x *= a; v.y *= a; v.z *= a; v.w *= a;
            float* dst = ((bb & 1) ? s_xO : s_xE) + (bb >> 1)*PI + k4;
            *(float4*)dst = v;
        }

        // S1: m = tanh(h @ dw0^T + db0)
        do_stage(wD0, s_inE, s_inO, inE, inO, s_red, tid,
            [&](int bb,int k){ return *(const float4*)&g_h[(b0+bb)*Hv + k]; },
            [&](float aE,float aO){
                g_m[(b0+bE)*Hv + c] = tanhf(aE + db0c);
                g_m[(b0+bO)*Hv + c] = tanhf(aO + db0c); });
        gbar(ctr, (++nbar)*32);
        // S2: k1 = tanh(m @ dw1^T + db1) * td
        do_stage(wD1, s_inE, s_inO, inE, inO, s_red, tid,
            [&](int bb,int k){ return *(const float4*)&g_m[(b0+bb)*Hv + k]; },
            [&](float aE,float aO){
                k1E = tanhf(aE + db1c) * tdE; k1O = tanhf(aO + db1c) * tdO;
                g_k1[(b0+bE)*Hv + c] = k1E;   g_k1[(b0+bO)*Hv + c] = k1O; });
        gbar(ctr, (++nbar)*32);
        // S3: m = tanh((h + k1/3) @ dw0^T + db0)
        do_stage(wD0, s_inE, s_inO, inE, inO, s_red, tid,
            [&](int bb,int k){ int i=(b0+bb)*Hv+k;
                float4 h4=*(const float4*)&g_h[i], a4=*(const float4*)&g_k1[i];
                return make_float4(fmaf(1.f/3.f,a4.x,h4.x), fmaf(1.f/3.f,a4.y,h4.y),
                                   fmaf(1.f/3.f,a4.z,h4.z), fmaf(1.f/3.f,a4.w,h4.w)); },
            [&](float aE,float aO){
                g_m[(b0+bE)*Hv + c] = tanhf(aE + db0c);
                g_m[(b0+bO)*Hv + c] = tanhf(aO + db0c); });
        gbar(ctr, (++nbar)*32);
        // S4: k2
        do_stage(wD1, s_inE, s_inO, inE, inO, s_red, tid,
            [&](int bb,int k){ return *(const float4*)&g_m[(b0+bb)*Hv + k]; },
            [&](float aE,float aO){
                k2E = tanhf(aE + db1c) * tdE; k2O = tanhf(aO + db1c) * tdO;
                g_k2[(b0+bE)*Hv + c] = k2E;   g_k2[(b0+bO)*Hv + c] = k2O; });
        gbar(ctr, (++nbar)*32);
        // S5: m = tanh((h + k2 - k1/3) @ dw0^T + db0)
        do_stage(wD0, s_inE, s_inO, inE, inO, s_red, tid,
            [&](int bb,int k){ int i=(b0+bb)*Hv+k;
                float4 h4=*(const float4*)&g_h[i], a4=*(const float4*)&g_k1[i],
                       c4=*(const float4*)&g_k2[i];
                return make_float4(h4.x+c4.x-(1.f/3.f)*a4.x, h4.y+c4.y-(1.f/3.f)*a4.y,
                                   h4.z+c4.z-(1.f/3.f)*a4.z, h4.w+c4.w-(1.f/3.f)*a4.w); },
            [&](float aE,float aO){
                g_m[(b0+bE)*Hv + c] = tanhf(aE + db0c);
                g_m[(b0+bO)*Hv + c] = tanhf(aO + db0c); });
        gbar(ctr, (++nbar)*32);
        // S6: k3
        do_stage(wD1, s_inE, s_inO, inE, inO, s_red, tid,
            [&](int bb,int k){ return *(const float4*)&g_m[(b0+bb)*Hv + k]; },
            [&](float aE,float aO){
                k3E = tanhf(aE + db1c) * tdE; k3O = tanhf(aO + db1c) * tdO;
                g_k3[(b0+bE)*Hv + c] = k3E;   g_k3[(b0+bO)*Hv + c] = k3O; });
        gbar(ctr, (++nbar)*32);
        // S7: m = tanh((h + k1 - k2 + k3) @ dw0^T + db0)
        do_stage(wD0, s_inE, s_inO, inE, inO, s_red, tid,
            [&](int bb,int k){ int i=(b0+bb)*Hv+k;
                float4 h4=*(const float4*)&g_h[i], a4=*(const float4*)&g_k1[i],
                       c4=*(const float4*)&g_k2[i], d4=*(const float4*)&g_k3[i];
                return make_float4(h4.x+a4.x-c4.x+d4.x, h4.y+a4.y-c4.y+d4.y,
                                   h4.z+a4.z-c4.z+d4.z, h4.w+a4.w-c4.w+d4.w); },
            [&](float aE,float aO){
                g_m[(b0+bE)*Hv + c] = tanhf(aE + db0c);
                g_m[(b0+bO)*Hv + c] = tanhf(aO + db0c); });
        gbar(ctr, (++nbar)*32);
        // S8: k4 ; h_ode = h + (k1 + 3(k2+k3) + k4)/8
        do_stage(wD1, s_inE, s_inO, inE, inO, s_red, tid,
            [&](int bb,int k){ return *(const float4*)&g_m[(b0+bb)*Hv + k]; },
            [&](float aE,float aO){
                float k4E = tanhf(aE + db1c) * tdE;
                float k4O = tanhf(aO + db1c) * tdO;
                float hE = g_h[(b0+bE)*Hv + c];
                float hO = g_h[(b0+bO)*Hv + c];
                hoE = hE + (k1E + 3.f*(k2E + k3E) + k4E) * 0.125f;
                hoO = hO + (k1O + 3.f*(k2O + k3O) + k4O) * 0.125f;
                g_ho[(b0+bE)*Hv + c] = hoE;
                g_ho[(b0+bO)*Hv + c] = hoO; });
        gbar(ctr, (++nbar)*32);
        // S9: GRU cell. r/z merge x- and h-parts; n keeps them separate.
        stage512(s_inE, s_inO, tid,
            [&](int bb,int k){ return *(const float4*)&g_ho[(b0+bb)*Hv + k]; });
        __syncthreads();
        {
            ull arE=0,arO=0,azE=0,azO=0,anE=0,anO=0,xnE=0,xnO=0;
            {
                const ulonglong2* __restrict__ e2 = (const ulonglong2*)inE;
                const ulonglong2* __restrict__ o2 = (const ulonglong2*)inO;
                const ulonglong2* __restrict__ r2 = (const ulonglong2*)(s_whh + c_loc*PH + kbase);
                const ulonglong2* __restrict__ z2 = (const ulonglong2*)(s_whh + (CPB + c_loc)*PH + kbase);
                const ulonglong2* __restrict__ n2 = (const ulonglong2*)(s_whh + (2*CPB + c_loc)*PH + kbase);
                #pragma unroll 8
                for (int j = 0; j < 64; j++) {
                    ulonglong2 e = e2[j], o = o2[j];
                    ulonglong2 wr = r2[j], wz = z2[j], wn = n2[j];
                    ffma2(arE, wr.x, e.x); ffma2(arE, wr.y, e.y);
                    ffma2(arO, wr.x, o.x); ffma2(arO, wr.y, o.y);
                    ffma2(azE, wz.x, e.x); ffma2(azE, wz.y, e.y);
                    ffma2(azO, wz.x, o.x); ffma2(azO, wz.y, o.y);
                    ffma2(anE, wn.x, e.x); ffma2(anE, wn.y, e.y);
                    ffma2(anO, wn.x, o.x); ffma2(anO, wn.y, o.y);
                }
            }
            {   // x part: K=256 split as kh*128; w_ih from global (L1-resident)
                int kx = kh << 7;
                const ulonglong2* __restrict__ e2 = (const ulonglong2*)(s_xE + p*PI + kx);
                const ulonglong2* __restrict__ o2 = (const ulonglong2*)(s_xO + p*PI + kx);
                const ulonglong2* __restrict__ r2 = (const ulonglong2*)(w_ih + (size_t)c*Iv + kx);
                const ulonglong2* __restrict__ z2 = (const ulonglong2*)(w_ih + (size_t)(Hv + c)*Iv + kx);
                const ulonglong2* __restrict__ n2 = (const ulonglong2*)(w_ih + (size_t)(2*Hv + c)*Iv + kx);
                #pragma unroll 8
                for (int j = 0; j < 32; j++) {
                    ulonglong2 e = e2[j], o = o2[j];
                    ulonglong2 wr = r2[j], wz = z2[j], wn = n2[j];
                    ffma2(arE, wr.x, e.x); ffma2(arE, wr.y, e.y);
                    ffma2(arO, wr.x, o.x); ffma2(arO, wr.y, o.y);
                    ffma2(azE, wz.x, e.x); ffma2(azE, wz.y, e.y);
                    ffma2(azO, wz.x, o.x); ffma2(azO, wz.y, o.y);
                    ffma2(xnE, wn.x, e.x); ffma2(xnE, wn.y, e.y);
                    ffma2(xnO, wn.x, o.x); ffma2(xnO, wn.y, o.y);
                }
            }
            float2* R2 = (float2*)s_red;
            if (tid >= 128) {
                int i = tid - 128;
                R2[i]       = make_float2(hsum1(arE), hsum1(arO));
                R2[128 + i] = make_float2(hsum1(azE), hsum1(azO));
                R2[256 + i] = make_float2(hsum1(anE), hsum1(anO));
                R2[384 + i] = make_float2(hsum1(xnE), hsum1(xnO));
            }
            __syncthreads();
            if (tid < 128) {
                float2 vr = R2[tid], vz = R2[128+tid], vn = R2[256+tid], vx = R2[384+tid];
                float arT = hsum1(arE) + vr.x, arU = hsum1(arO) + vr.y;
                float azT = hsum1(azE) + vz.x, azU = hsum1(azO) + vz.y;
                float anT = hsum1(anE) + vn.x, anU = hsum1(anO) + vn.y;
                float xnT = hsum1(xnE) + vx.x, xnU = hsum1(xnO) + vx.y;
                float rE_ = sigm(arT + bir + bhr), rO_ = sigm(arU + bir + bhr);
                float zE_ = sigm(azT + biz + bhz), zO_ = sigm(azU + biz + bhz);
                float nE_ = tanhf(xnT + bin_ + rE_*(anT + bhn));
                float nO_ = tanhf(xnU + bin_ + rO_*(anU + bhn));
                float hnE = (1.f - zE_)*nE_ + zE_*hoE;
                float hnO = (1.f - zO_)*nO_ + zO_*hoO;
                g_h[(b0+bE)*Hv + c] = hnE;
                g_h[(b0+bO)*Hv + c] = hnO;
                out[(size_t)(b0+bE)*(Lv*Hv) + (size_t)t*Hv + c] = hnE;
                out[(size_t)(b0+bO)*(Lv*Hv) + (size_t)t*Hv + c] = hnO;
                if (t == slenE - 1) out[(size_t)Bv*Lv*Hv + (b0+bE)*Hv + c] = hnE;
                if (t == slenO - 1) out[(size_t)Bv*Lv*Hv + (b0+bO)*Hv + c] = hnO;
            }
        }
        // next loop-top gbar publishes g_h
    }
}

extern "C" void kernel_launch(void* const* d_in, const int* in_sizes, int n_in,
                              void* d_out, int out_size) {
    const float* x     = (const float*)d_in[0];
    const float* tdel  = (const float*)d_in[1];
    const float* w_ih  = (const float*)d_in[2];
    const float* w_hh  = (const float*)d_in[3];
    const float* b_ih  = (const float*)d_in[4];
    const float* b_hh  = (const float*)d_in[5];
    const float* dw0   = (const float*)d_in[6];
    const float* db0   = (const float*)d_in[7];
    const float* dw1   = (const float*)d_in[8];
    const float* db1   = (const float*)d_in[9];
    const float* h0    = (const float*)d_in[10];
    const int*   seq   = (const int*)d_in[11];
    float* out = (float*)d_out;

    // smem floats: 5*16*PH (weights) + 16*PH (in E/O) + 16*PI (x E/O) + 1024 red + 32
    size_t smem_floats = (size_t)(5*CPB*PH + 16*PH + 16*PI + 1024 + 32);
    size_t smem_bytes  = smem_floats * sizeof(float);
    cudaFuncSetAttribute(odegru_main, cudaFuncAttributeMaxDynamicSharedMemorySize,
                         (int)smem_bytes);

    init_bar_kernel<<<1, 128>>>();
    odegru_main<<<NBLK, NT, smem_bytes>>>(x, tdel, w_ih, w_hh, b_ih, b_hh,
                                          dw0, db0, dw1, db1, h0, seq, out);
}

// round 12
// speedup vs baseline: 1.5797x; 1.0056x over previous
#include <cuda_runtime.h>
#include <cstdint>

#define Bv 64
#define Lv 512
#define Iv 256
#define Hv 512

#define CG 32
#define RG 4
#define NBLK (CG*RG)
#define CPB 16
#define BPB 16
#define NT 512

#define PH 516     // pitch: 516 mod 32 == 4 -> conflict-free LDS.128

typedef unsigned long long ull;

// Global state, layout [b][k]
__device__ float g_h [Bv*Hv];
__device__ float g_m [Bv*Hv];
__device__ float g_k1[Bv*Hv];
__device__ float g_k2[Bv*Hv];
__device__ float g_k3[Bv*Hv];
__device__ float g_ho[Bv*Hv];
__device__ unsigned g_bar[RG*32];

__device__ __forceinline__ void ffma2(ull& a, ull x, ull y){
    asm("fma.rn.f32x2 %0, %1, %2, %0;" : "+l"(a) : "l"(x), "l"(y));
}
__device__ __forceinline__ float lo32(ull v){ return __int_as_float((unsigned)v); }
__device__ __forceinline__ float hi32(ull v){ return __int_as_float((unsigned)(v>>32)); }
__device__ __forceinline__ float hsum1(ull a){ return lo32(a)+hi32(a); }
__device__ __forceinline__ float sigm(float v){ return 1.0f/(1.0f+expf(-v)); }

// ---- release/acquire group barrier: no threadfence -> no CCTL.IVALL -----
__device__ __forceinline__ void bar_arrive(unsigned* c){
    asm volatile("red.release.gpu.global.add.u32 [%0], 1;" :: "l"(c) : "memory");
}
__device__ __forceinline__ unsigned ld_acq(const unsigned* c){
    unsigned v;
    asm volatile("ld.acquire.gpu.global.u32 %0, [%1];" : "=r"(v) : "l"(c) : "memory");
    return v;
}
__device__ __forceinline__ void gbar(unsigned* ctr, unsigned target){
    __syncthreads();
    if (threadIdx.x == 0){
        bar_arrive(ctr);
        while (ld_acq(ctr) < target) { }
    }
    __syncthreads();
}

// ---- stage 16 rows x 512 k into even/odd-batch smem (pitch PH) ----------
template <typename F>
__device__ __forceinline__ void stage512(float* __restrict__ sE, float* __restrict__ sO,
                                         int tid, F ld){
    #pragma unroll
    for (int ii = 0; ii < 4; ii++){
        int item = tid + ii*NT;          // 2048 float4 items
        int bb = item >> 7;
        int k4 = (item & 127) << 2;
        float4 v = ld(bb, k4);
        float* dst = ((bb & 1) ? sO : sE) + (bb >> 1)*PH + k4;
        *(float4*)dst = v;
    }
}

// ---- K=128 slice GEMV: packed f32x2, 2 batches, 4 chains ----------------
__device__ __forceinline__ void gemv128(const float* __restrict__ w,
                                        const float* __restrict__ rE,
                                        const float* __restrict__ rO,
                                        float& sE, float& sO){
    const ulonglong2* __restrict__ w2 = (const ulonglong2*)w;
    const ulonglong2* __restrict__ e2 = (const ulonglong2*)rE;
    const ulonglong2* __restrict__ o2 = (const ulonglong2*)rO;
    ull aE0=0, aE1=0, aO0=0, aO1=0;
    #pragma unroll
    for (int j = 0; j < 32; j++){
        ulonglong2 wv = w2[j], e = e2[j], o = o2[j];
        ffma2(aE0, wv.x, e.x); ffma2(aE1, wv.y, e.y);
        ffma2(aO0, wv.x, o.x); ffma2(aO1, wv.y, o.y);
    }
    sE = hsum1(aE0) + hsum1(aE1);
    sO = hsum1(aO0) + hsum1(aO1);
}

// stage + gemv + 4-way K reduce + epilogue (epi on kq==0 threads)
template <typename FL, typename FE>
__device__ __forceinline__ void do_stage(const float* __restrict__ w,
                                         float* sE, float* sO,
                                         const float* inE, const float* inO,
                                         float* s_red, int tid, int kq, int slot,
                                         FL ld, FE epi){
    stage512(sE, sO, tid, ld);
    __syncthreads();
    float vE, vO;
    gemv128(w, inE, inO, vE, vO);
    float2* R = (float2*)s_red;
    if (kq) R[(kq-1)*128 + slot] = make_float2(vE, vO);
    __syncthreads();
    if (kq == 0){
        float2 p1 = R[slot], p2 = R[128+slot], p3 = R[256+slot];
        epi(vE + p1.x + p2.x + p3.x, vO + p1.y + p2.y + p3.y);
    }
}

__global__ void init_bar_kernel(){
    if (threadIdx.x < RG*32) g_bar[threadIdx.x] = 0;
}

__global__ void __launch_bounds__(NT, 1)
odegru_main(const float* __restrict__ x,     const float* __restrict__ tdel,
            const float* __restrict__ w_ih,  const float* __restrict__ w_hh,
            const float* __restrict__ b_ih,  const float* __restrict__ b_hh,
            const float* __restrict__ dw0,   const float* __restrict__ db0,
            const float* __restrict__ dw1,   const float* __restrict__ db1,
            const float* __restrict__ h0,    const int*   __restrict__ seq_lens,
            float* __restrict__ out){
    extern __shared__ float smem[];
    float* s_dw0 = smem;                    // 16*PH
    float* s_dw1 = s_dw0 + CPB*PH;
    float* s_whh = s_dw1 + CPB*PH;          // 3*16*PH
    float* s_inE = s_whh + 3*CPB*PH;        // 8*PH
    float* s_inO = s_inE + 8*PH;            // 8*PH
    float* s_red = s_inO + 8*PH;            // 3072 floats (S9 uses all)

    const int blk = blockIdx.x;
    const int cg  = blk & (CG-1);
    const int rg  = blk >> 5;
    const int c0  = cg*CPB, b0 = rg*BPB;
    const int tid = threadIdx.x;

    const int wid    = tid >> 5;
    const int lane   = tid & 31;
    const int q      = wid & 3;          // col quad
    const int kq     = wid >> 2;         // K quarter 0..3
    const int colIdx = lane & 3;
    const int p      = lane >> 2;        // batch pair 0..7
    const int c_loc  = (q<<2) + colIdx;
    const int c      = c0 + c_loc;
    const int bE     = p<<1, bO = bE+1;
    const int kbase  = kq << 7;          // 0,128,256,384
    const int slot   = q*32 + lane;      // 0..127, same across kq groups

    // persistent weight slices (float4, pitch PH)
    #pragma unroll
    for (int ii = 0; ii < 4; ii++){
        int item = tid + ii*NT;
        int r = item >> 7, k4 = (item & 127) << 2;
        *(float4*)&s_dw0[r*PH + k4] = *(const float4*)&dw0[(c0+r)*Hv + k4];
        *(float4*)&s_dw1[r*PH + k4] = *(const float4*)&dw1[(c0+r)*Hv + k4];
    }
    #pragma unroll
    for (int g = 0; g < 3; g++){
        #pragma unroll
        for (int ii = 0; ii < 4; ii++){
            int item = tid + ii*NT;
            int r = item >> 7, k4 = (item & 127) << 2;
            *(float4*)&s_whh[(g*CPB + r)*PH + k4] =
                *(const float4*)&w_hh[(g*Hv + c0 + r)*Hv + k4];
        }
    }

    const float db0c = db0[c], db1c = db1[c];
    const float bhr = b_hh[c], bhz = b_hh[Hv+c], bhn = b_hh[2*Hv+c];
    const float bir = b_ih[c], biz = b_ih[Hv+c], bin_ = b_ih[2*Hv+c];
    const int slenE = seq_lens[b0+bE], slenO = seq_lens[b0+bO];

    // init hidden state (block owns its 16x16 tile); also register copy
    if (tid < 256){
        int ty_i = tid >> 4, tx_i = tid & 15;
        __stcg(&g_h[(b0+tx_i)*Hv + (c0+ty_i)], h0[c0+ty_i]);
    }
    float hprevE = h0[c], hprevO = h0[c];

    unsigned* ctr = &g_bar[rg*32];
    unsigned nbar = 0;

    const float* wD0 = s_dw0 + c_loc*PH + kbase;
    const float* wD1 = s_dw1 + c_loc*PH + kbase;
    const float* inE = s_inE + p*PH + kbase;
    const float* inO = s_inO + p*PH + kbase;

    float k1E=0.f,k1O=0.f,k2E=0.f,k2O=0.f,k3E=0.f,k3O=0.f,hoE=0.f,hoO=0.f;

    for (int t = 0; t < Lv; t++){
        // per-step mask / dt (registers only; overlaps barrier wait)
        const float actE = (t < slenE) ? 1.0f : 0.0f;
        const float actO = (t < slenO) ? 1.0f : 0.0f;
        const float tdE = actE * __ldg(&tdel[(b0+bE)*Lv + t]);
        const float tdO = actO * __ldg(&tdel[(b0+bO)*Lv + t]);

        gbar(ctr, (++nbar)*32);              // publishes previous h

        // S1: m = tanh(h @ dw0^T + db0)
        do_stage(wD0, s_inE, s_inO, inE, inO, s_red, tid, kq, slot,
            [&](int bb,int k){ return __ldcg((const float4*)&g_h[(b0+bb)*Hv + k]); },
            [&](float aE,float aO){
                __stcg(&g_m[(b0+bE)*Hv + c], tanhf(aE + db0c));
                __stcg(&g_m[(b0+bO)*Hv + c], tanhf(aO + db0c)); });
        gbar(ctr, (++nbar)*32);
        // S2: k1 = tanh(m @ dw1^T + db1) * td
        do_stage(wD1, s_inE, s_inO, inE, inO, s_red, tid, kq, slot,
            [&](int bb,int k){ return __ldcg((const float4*)&g_m[(b0+bb)*Hv + k]); },
            [&](float aE,float aO){
                k1E = tanhf(aE + db1c) * tdE; k1O = tanhf(aO + db1c) * tdO;
                __stcg(&g_k1[(b0+bE)*Hv + c], k1E);
                __stcg(&g_k1[(b0+bO)*Hv + c], k1O); });
        gbar(ctr, (++nbar)*32);
        // S3: m = tanh((h + k1/3) @ dw0^T + db0)
        do_stage(wD0, s_inE, s_inO, inE, inO, s_red, tid, kq, slot,
            [&](int bb,int k){ int i=(b0+bb)*Hv+k;
                float4 h4=__ldcg((const float4*)&g_h[i]);
                float4 a4=__ldcg((const float4*)&g_k1[i]);
                return make_float4(fmaf(1.f/3.f,a4.x,h4.x), fmaf(1.f/3.f,a4.y,h4.y),
                                   fmaf(1.f/3.f,a4.z,h4.z), fmaf(1.f/3.f,a4.w,h4.w)); },
            [&](float aE,float aO){
                __stcg(&g_m[(b0+bE)*Hv + c], tanhf(aE + db0c));
                __stcg(&g_m[(b0+bO)*Hv + c], tanhf(aO + db0c)); });
        gbar(ctr, (++nbar)*32);
        // S4: k2
        do_stage(wD1, s_inE, s_inO, inE, inO, s_red, tid, kq, slot,
            [&](int bb,int k){ return __ldcg((const float4*)&g_m[(b0+bb)*Hv + k]); },
            [&](float aE,float aO){
                k2E = tanhf(aE + db1c) * tdE; k2O = tanhf(aO + db1c) * tdO;
                __stcg(&g_k2[(b0+bE)*Hv + c], k2E);
                __stcg(&g_k2[(b0+bO)*Hv + c], k2O); });
        gbar(ctr, (++nbar)*32);
        // S5: m = tanh((h + k2 - k1/3) @ dw0^T + db0)
        do_stage(wD0, s_inE, s_inO, inE, inO, s_red, tid, kq, slot,
            [&](int bb,int k){ int i=(b0+bb)*Hv+k;
                float4 h4=__ldcg((const float4*)&g_h[i]);
                float4 a4=__ldcg((const float4*)&g_k1[i]);
                float4 c4=__ldcg((const float4*)&g_k2[i]);
                return make_float4(h4.x+c4.x-(1.f/3.f)*a4.x, h4.y+c4.y-(1.f/3.f)*a4.y,
                                   h4.z+c4.z-(1.f/3.f)*a4.z, h4.w+c4.w-(1.f/3.f)*a4.w); },
            [&](float aE,float aO){
                __stcg(&g_m[(b0+bE)*Hv + c], tanhf(aE + db0c));
                __stcg(&g_m[(b0+bO)*Hv + c], tanhf(aO + db0c)); });
        gbar(ctr, (++nbar)*32);
        // S6: k3
        do_stage(wD1, s_inE, s_inO, inE, inO, s_red, tid, kq, slot,
            [&](int bb,int k){ return __ldcg((const float4*)&g_m[(b0+bb)*Hv + k]); },
            [&](float aE,float aO){
                k3E = tanhf(aE + db1c) * tdE; k3O = tanhf(aO + db1c) * tdO;
                __stcg(&g_k3[(b0+bE)*Hv + c], k3E);
                __stcg(&g_k3[(b0+bO)*Hv + c], k3O); });
        gbar(ctr, (++nbar)*32);
        // S7: m = tanh((h + k1 - k2 + k3) @ dw0^T + db0)
        do_stage(wD0, s_inE, s_inO, inE, inO, s_red, tid, kq, slot,
            [&](int bb,int k){ int i=(b0+bb)*Hv+k;
                float4 h4=__ldcg((const float4*)&g_h[i]);
                float4 a4=__ldcg((const float4*)&g_k1[i]);
                float4 c4=__ldcg((const float4*)&g_k2[i]);
                float4 d4=__ldcg((const float4*)&g_k3[i]);
                return make_float4(h4.x+a4.x-c4.x+d4.x, h4.y+a4.y-c4.y+d4.y,
                                   h4.z+a4.z-c4.z+d4.z, h4.w+a4.w-c4.w+d4.w); },
            [&](float aE,float aO){
                __stcg(&g_m[(b0+bE)*Hv + c], tanhf(aE + db0c));
                __stcg(&g_m[(b0+bO)*Hv + c], tanhf(aO + db0c)); });
        gbar(ctr, (++nbar)*32);
        // S8: k4 ; h_ode = h + (k1 + 3(k2+k3) + k4)/8  (h from registers)
        do_stage(wD1, s_inE, s_inO, inE, inO, s_red, tid, kq, slot,
            [&](int bb,int k){ return __ldcg((const float4*)&g_m[(b0+bb)*Hv + k]); },
            [&](float aE,float aO){
                float k4E = tanhf(aE + db1c) * tdE;
                float k4O = tanhf(aO + db1c) * tdO;
                hoE = hprevE + (k1E + 3.f*(k2E + k3E) + k4E) * 0.125f;
                hoO = hprevO + (k1O + 3.f*(k2O + k3O) + k4O) * 0.125f;
                __stcg(&g_ho[(b0+bE)*Hv + c], hoE);
                __stcg(&g_ho[(b0+bO)*Hv + c], hoO); });
        gbar(ctr, (++nbar)*32);
        // S9: GRU cell. h-part from smem, x-part streamed from L2, mask applied post-sum.
        stage512(s_inE, s_inO, tid,
            [&](int bb,int k){ return __ldcg((const float4*)&g_ho[(b0+bb)*Hv + k]); });
        __syncthreads();
        {
            ull arE=0,arO=0,azE=0,azO=0,anE=0,anO=0;
            {
                const ulonglong2* __restrict__ e2 = (const ulonglong2*)inE;
                const ulonglong2* __restrict__ o2 = (const ulonglong2*)inO;
                const ulonglong2* __restrict__ r2 = (const ulonglong2*)(s_whh + c_loc*PH + kbase);
                const ulonglong2* __restrict__ z2 = (const ulonglong2*)(s_whh + (CPB + c_loc)*PH + kbase);
                const ulonglong2* __restrict__ n2 = (const ulonglong2*)(s_whh + (2*CPB + c_loc)*PH + kbase);
                #pragma unroll 8
                for (int j = 0; j < 32; j++){
                    ulonglong2 e = e2[j], o = o2[j];
                    ulonglong2 wr = r2[j], wz = z2[j], wn = n2[j];
                    ffma2(arE, wr.x, e.x); ffma2(arE, wr.y, e.y);
                    ffma2(arO, wr.x, o.x); ffma2(arO, wr.y, o.y);
                    ffma2(azE, wz.x, e.x); ffma2(azE, wz.y, e.y);
                    ffma2(azO, wz.x, o.x); ffma2(azO, wz.y, o.y);
                    ffma2(anE, wn.x, e.x); ffma2(anE, wn.y, e.y);
                    ffma2(anO, wn.x, o.x); ffma2(anO, wn.y, o.y);
                }
            }
            ull xrE=0,xrO=0,xzE=0,xzO=0,xnE=0,xnO=0;
            {
                const int kx = kq << 6;   // 64 k per quarter of Iv=256
                const float* xE = x + (size_t)(b0+bE)*(Lv*Iv) + (size_t)t*Iv + kx;
                const float* xO = x + (size_t)(b0+bO)*(Lv*Iv) + (size_t)t*Iv + kx;
                const ulonglong2* __restrict__ r2 = (const ulonglong2*)(w_ih + (size_t)c*Iv + kx);
                const ulonglong2* __restrict__ z2 = (const ulonglong2*)(w_ih + (size_t)(Hv + c)*Iv + kx);
                const ulonglong2* __restrict__ n2 = (const ulonglong2*)(w_ih + (size_t)(2*Hv + c)*Iv + kx);
                #pragma unroll 4
                for (int j = 0; j < 16; j++){
                    float4 ef = __ldcg((const float4*)(xE + 4*j));
                    float4 of = __ldcg((const float4*)(xO + 4*j));
                    ulonglong2 e = *(ulonglong2*)&ef;
                    ulonglong2 o = *(ulonglong2*)&of;
                    ulonglong2 wr = r2[j], wz = z2[j], wn = n2[j];
                    ffma2(xrE, wr.x, e.x); ffma2(xrE, wr.y, e.y);
                    ffma2(xrO, wr.x, o.x); ffma2(xrO, wr.y, o.y);
                    ffma2(xzE, wz.x, e.x); ffma2(xzE, wz.y, e.y);
                    ffma2(xzO, wz.x, o.x); ffma2(xzO, wz.y, o.y);
                    ffma2(xnE, wn.x, e.x); ffma2(xnE, wn.y, e.y);
                    ffma2(xnO, wn.x, o.x); ffma2(xnO, wn.y, o.y);
                }
            }
            // per-thread partials (mask applied to x-part: linear, so post-sum is exact)
            float prE = hsum1(arE) + actE*hsum1(xrE);
            float prO = hsum1(arO) + actO*hsum1(xrO);
            float pzE = hsum1(azE) + actE*hsum1(xzE);
            float pzO = hsum1(azO) + actO*hsum1(xzO);
            float pnE = hsum1(anE), pnO = hsum1(anO);
            float pxE = actE*hsum1(xnE), pxO = actO*hsum1(xnO);
            float2* R = (float2*)s_red;
            if (kq){
                int off = (kq-1)*512;
                R[off +        slot] = make_float2(prE, prO);
                R[off + 128 +  slot] = make_float2(pzE, pzO);
                R[off + 256 +  slot] = make_float2(pnE, pnO);
                R[off + 384 +  slot] = make_float2(pxE, pxO);
            }
            __syncthreads();
            if (kq == 0){
                float arT=prE, arU=prO, azT=pzE, azU=pzO, anT=pnE, anU=pnO, xnT=pxE, xnU=pxO;
                #pragma unroll
                for (int h = 0; h < 3; h++){
                    float2 a = R[h*512 +        slot]; arT += a.x; arU += a.y;
                    float2 bq= R[h*512 + 128 +  slot]; azT += bq.x; azU += bq.y;
                    float2 cc= R[h*512 + 256 +  slot]; anT += cc.x; anU += cc.y;
                    float2 d = R[h*512 + 384 +  slot]; xnT += d.x; xnU += d.y;
                }
                float rE_ = sigm(arT + bir + bhr), rO_ = sigm(arU + bir + bhr);
                float zE_ = sigm(azT + biz + bhz), zO_ = sigm(azU + biz + bhz);
                float nE_ = tanhf(xnT + bin_ + rE_*(anT + bhn));
                float nO_ = tanhf(xnU + bin_ + rO_*(anU + bhn));
                float hnE = (1.f - zE_)*nE_ + zE_*hoE;
                float hnO = (1.f - zO_)*nO_ + zO_*hoO;
                __stcg(&g_h[(b0+bE)*Hv + c], hnE);
                __stcg(&g_h[(b0+bO)*Hv + c], hnO);
                out[(size_t)(b0+bE)*(Lv*Hv) + (size_t)t*Hv + c] = hnE;
                out[(size_t)(b0+bO)*(Lv*Hv) + (size_t)t*Hv + c] = hnO;
                if (t == slenE - 1) out[(size_t)Bv*Lv*Hv + (b0+bE)*Hv + c] = hnE;
                if (t == slenO - 1) out[(size_t)Bv*Lv*Hv + (b0+bO)*Hv + c] = hnO;
                hprevE = hnE; hprevO = hnO;
            }
        }
        // loop-top gbar publishes g_h for the next step
    }
}

extern "C" void kernel_launch(void* const* d_in, const int* in_sizes, int n_in,
                              void* d_out, int out_size){
    const float* x     = (const float*)d_in[0];
    const float* tdel  = (const float*)d_in[1];
    const float* w_ih  = (const float*)d_in[2];
    const float* w_hh  = (const float*)d_in[3];
    const float* b_ih  = (const float*)d_in[4];
    const float* b_hh  = (const float*)d_in[5];
    const float* dw0   = (const float*)d_in[6];
    const float* db0   = (const float*)d_in[7];
    const float* dw1   = (const float*)d_in[8];
    const float* db1   = (const float*)d_in[9];
    const float* h0    = (const float*)d_in[10];
    const int*   seq   = (const int*)d_in[11];
    float* out = (float*)d_out;

    // smem floats: 5*16*PH (weights) + 16*PH (in E/O) + 3072 (reduce)
    size_t smem_floats = (size_t)(5*CPB*PH + 16*PH + 3072);
    size_t smem_bytes  = smem_floats * sizeof(float);   // 210,432 B
    cudaFuncSetAttribute(odegru_main, cudaFuncAttributeMaxDynamicSharedMemorySize,
                         (int)smem_bytes);

    init_bar_kernel<<<1, 128>>>();
    odegru_main<<<NBLK, NT, smem_bytes>>>(x, tdel, w_ih, w_hh, b_ih, b_hh,
                                          dw0, db0, dw1, db1, h0, seq, out);
}